// round 11
// baseline (speedup 1.0000x reference)
#include <cuda_runtime.h>
#include <cstdint>

#define CM_B    64
#define CM_T    256
#define CM_NI   512
#define CM_NO   512
#define CM_NOBS 128
#define ETA     0.01f

typedef unsigned long long u64;

// Scratch: C[b][m][n], m<256 -> G[s=m][t=n]; m>=256 -> P0[o=m-256][t=n]
__device__ float g_scratch[(size_t)CM_B * 384 * 256];

// ---------------- helpers ----------------
__device__ __forceinline__ uint32_t f2tf(float x) {
    uint32_t r; asm("cvt.rna.tf32.f32 %0, %1;" : "=r"(r) : "f"(x)); return r;
}
__device__ __forceinline__ u64 pk2(float lo, float hi) {
    u64 r; asm("mov.b64 %0, {%1, %2};" : "=l"(r) : "f"(lo), "f"(hi)); return r;
}
__device__ __forceinline__ u64 ffma2(u64 a, u64 b, u64 c) {
    u64 d; asm("fma.rn.f32x2 %0, %1, %2, %3;" : "=l"(d) : "l"(a), "l"(b), "l"(c)); return d;
}
__device__ __forceinline__ float sigmoidf_fast(float v) {
    return __fdividef(1.0f, 1.0f + __expf(-v));
}
// mma.m16n8k8 tf32, D += A*B (D=C in place)
__device__ __forceinline__ void mma8(float& d0, float& d1, float& d2, float& d3,
                                     uint32_t a0, uint32_t a1, uint32_t a2, uint32_t a3,
                                     uint32_t b0, uint32_t b1) {
    asm volatile(
        "mma.sync.aligned.m16n8k8.row.col.f32.tf32.tf32.f32 "
        "{%0,%1,%2,%3}, {%4,%5,%6,%7}, {%8,%9}, {%0,%1,%2,%3};"
        : "+f"(d0), "+f"(d1), "+f"(d2), "+f"(d3)
        : "r"(a0), "r"(a1), "r"(a2), "r"(a3), "r"(b0), "r"(b1));
}

// ---------------- Kernel 1: batched GEMM C = [X;W_obs] * X^T (tf32x3) ----------------
#define KC   16
#define APAD 17

__constant__ int c_mt[5] = {0, 0, 1, 2, 2};
__constant__ int c_nt[5] = {0, 1, 1, 0, 1};

__global__ __launch_bounds__(256)
void gemm_kernel(const float* __restrict__ X,
                 const float* __restrict__ Wi,
                 const int*   __restrict__ obs) {
    __shared__ float Ah[128 * APAD], Al[128 * APAD];
    __shared__ float Bh[128 * APAD], Bl[128 * APAD];

    const int b     = blockIdx.x;
    const int mtile = c_mt[blockIdx.y];
    const int ntile = c_nt[blockIdx.y];

    const int tid  = threadIdx.x;
    const int warp = tid >> 5, lane = tid & 31;
    const int wm   = warp >> 1, wn = warp & 1;      // warp grid 4x2 over 128x128
    const int gID  = lane >> 2, tig = lane & 3;

    // loading role: 2 threads per row, 8 cols each
    const int lrow  = tid >> 1;
    const int lcol0 = (tid & 1) * 8;
    const int arow  = mtile * 128 + lrow;
    const float* aptr = (arow < 256)
        ? X  + ((size_t)b * CM_T  + arow) * CM_NI
        : Wi + ((size_t)b * CM_NO + __ldg(&obs[arow - 256])) * CM_NI;
    const float* bptr = X + ((size_t)b * CM_T + ntile * 128 + lrow) * CM_NI;

    float acc[2][8][4];
    #pragma unroll
    for (int i = 0; i < 2; ++i)
        #pragma unroll
        for (int j = 0; j < 8; ++j)
            #pragma unroll
            for (int q = 0; q < 4; ++q) acc[i][j][q] = 0.f;

    for (int ks = 0; ks < CM_NI; ks += KC) {
        // stage A and B slices, split hi/lo tf32
        #pragma unroll
        for (int h = 0; h < 2; ++h) {
            float4 v = *(const float4*)(aptr + ks + lcol0 + h * 4);
            float* dh = Ah + lrow * APAD + lcol0 + h * 4;
            float* dl = Al + lrow * APAD + lcol0 + h * 4;
            float c[4] = {v.x, v.y, v.z, v.w};
            #pragma unroll
            for (int q = 0; q < 4; ++q) {
                float hf = __uint_as_float(f2tf(c[q]));
                dh[q] = hf;
                dl[q] = __uint_as_float(f2tf(c[q] - hf));
            }
        }
        #pragma unroll
        for (int h = 0; h < 2; ++h) {
            float4 v = *(const float4*)(bptr + ks + lcol0 + h * 4);
            float* dh = Bh + lrow * APAD + lcol0 + h * 4;
            float* dl = Bl + lrow * APAD + lcol0 + h * 4;
            float c[4] = {v.x, v.y, v.z, v.w};
            #pragma unroll
            for (int q = 0; q < 4; ++q) {
                float hf = __uint_as_float(f2tf(c[q]));
                dh[q] = hf;
                dl[q] = __uint_as_float(f2tf(c[q] - hf));
            }
        }
        __syncthreads();

        #pragma unroll
        for (int kk = 0; kk < KC / 8; ++kk) {
            const int kb = kk * 8;
            // A fragments (2 m-frags), hi and lo
            uint32_t ahf[2][4], alf[2][4];
            #pragma unroll
            for (int mf = 0; mf < 2; ++mf) {
                const int m0 = wm * 32 + mf * 16;
                const int r0 = (m0 + gID) * APAD + kb;
                const int r1 = (m0 + gID + 8) * APAD + kb;
                ahf[mf][0] = __float_as_uint(Ah[r0 + tig]);
                ahf[mf][1] = __float_as_uint(Ah[r1 + tig]);
                ahf[mf][2] = __float_as_uint(Ah[r0 + tig + 4]);
                ahf[mf][3] = __float_as_uint(Ah[r1 + tig + 4]);
                alf[mf][0] = __float_as_uint(Al[r0 + tig]);
                alf[mf][1] = __float_as_uint(Al[r1 + tig]);
                alf[mf][2] = __float_as_uint(Al[r0 + tig + 4]);
                alf[mf][3] = __float_as_uint(Al[r1 + tig + 4]);
            }
            #pragma unroll
            for (int nf = 0; nf < 8; ++nf) {
                const int n0 = wn * 64 + nf * 8;
                const int rb = (n0 + gID) * APAD + kb;
                uint32_t bh0 = __float_as_uint(Bh[rb + tig]);
                uint32_t bh1 = __float_as_uint(Bh[rb + tig + 4]);
                uint32_t bl0 = __float_as_uint(Bl[rb + tig]);
                uint32_t bl1 = __float_as_uint(Bl[rb + tig + 4]);
                #pragma unroll
                for (int mf = 0; mf < 2; ++mf) {
                    float* d = acc[mf][nf];
                    mma8(d[0], d[1], d[2], d[3],
                         ahf[mf][0], ahf[mf][1], ahf[mf][2], ahf[mf][3], bh0, bh1);
                    mma8(d[0], d[1], d[2], d[3],
                         ahf[mf][0], ahf[mf][1], ahf[mf][2], ahf[mf][3], bl0, bl1);
                    mma8(d[0], d[1], d[2], d[3],
                         alf[mf][0], alf[mf][1], alf[mf][2], alf[mf][3], bh0, bh1);
                }
            }
        }
        __syncthreads();
    }

    // store: c0 (gID, 2tig), c1 (gID, 2tig+1), c2 (gID+8, 2tig), c3 (gID+8, 2tig+1)
    #pragma unroll
    for (int mf = 0; mf < 2; ++mf) {
        const int mrow = mtile * 128 + wm * 32 + mf * 16 + gID;
        #pragma unroll
        for (int nf = 0; nf < 8; ++nf) {
            const int ncol = ntile * 128 + wn * 64 + nf * 8 + 2 * tig;
            float* cp = g_scratch + ((size_t)b * 384 + mrow) * 256 + ncol;
            *(float2*)cp               = make_float2(acc[mf][nf][0], acc[mf][nf][1]);
            *(float2*)(cp + 8 * 256)   = make_float2(acc[mf][nf][2], acc[mf][nf][3]);
        }
    }
}

// ---------------- Kernel 2: blocked causal scan ----------------
// block = (batch, quarter of rows): 32 observed rows. pre[o][t] in smem.
#define PSTR 258      // even padding: f32x2-friendly, bank-spread
#define SC_THREADS 256

__global__ __launch_bounds__(SC_THREADS)
void scan_kernel(float* __restrict__ out) {
    __shared__ float pre[32 * PSTR];     // 33.0 KB
    __shared__ float gst[8 * PSTR];      //  8.3 KB
    __shared__ float ych[8 * 32];        //  1.0 KB

    const int bb    = blockIdx.x;
    const int b     = bb >> 2;
    const int obase = (bb & 3) * 32;
    const int tid   = threadIdx.x;

    const float* P0 = g_scratch + ((size_t)b * 384 + 256 + obase) * 256;
    const float* G  = g_scratch + (size_t)b * 384 * 256;
    float* outp     = out + (size_t)b * CM_T * CM_NOBS + obase;

    // init pre[o][t] = P0[o][t]
    for (int idx = tid; idx < 32 * 256; idx += SC_THREADS) {
        const int o = idx >> 8, t = idx & 255;
        pre[o * PSTR + t] = P0[o * 256 + t];
    }
    __syncthreads();

    for (int k = 0; k < 32; ++k) {
        const int t0 = k * 8;

        // stage G rows t0..t0+7 (full rows; only t>s entries are ever used)
        for (int idx = tid; idx < 8 * 256; idx += SC_THREADS) {
            const int s = idx >> 8, t = idx & 255;
            gst[s * PSTR + t] = G[(size_t)(t0 + s) * 256 + t];
        }
        __syncthreads();

        // serial phase: one warp, thread o
        if (tid < 32) {
            const int o = tid;
            float p[8];
            #pragma unroll
            for (int s = 0; s < 8; ++s) p[s] = pre[o * PSTR + t0 + s];
            float yl[8];
            #pragma unroll
            for (int s = 0; s < 8; ++s) {
                const float y = sigmoidf_fast(p[s]);
                yl[s] = y;
                outp[(size_t)(t0 + s) * CM_NOBS + o] = y;
                const float c = ETA * y;
                #pragma unroll
                for (int s2 = s + 1; s2 < 8; ++s2)
                    p[s2] += c * gst[s * PSTR + t0 + s2];
            }
            #pragma unroll
            for (int s = 0; s < 8; ++s) ych[s * 32 + o] = ETA * yl[s];
        }
        __syncthreads();

        // bulk phase: pre[o][t] += eta * sum_s y_s * G[t0+s][t], t >= t0+8
        if (k < 31) {
            const int o  = tid & 31;
            const int tq = tid >> 5;        // 0..7
            u64 cs[8];
            #pragma unroll
            for (int s = 0; s < 8; ++s) {
                const float c = ych[s * 32 + o];
                cs[s] = pk2(c, c);
            }
            float* prow = pre + o * PSTR;
            for (int t = t0 + 8 + tq * 2; t < 256; t += 16) {
                u64 a = *(u64*)(prow + t);
                #pragma unroll
                for (int s = 0; s < 8; ++s) {
                    const u64 g2 = *(const u64*)(gst + s * PSTR + t);
                    a = ffma2(cs[s], g2, a);
                }
                *(u64*)(prow + t) = a;
            }
        }
        __syncthreads();
    }
}

// ---------------- launch ----------------
extern "C" void kernel_launch(void* const* d_in, const int* in_sizes, int n_in,
                              void* d_out, int out_size) {
    const float* X   = (const float*)d_in[0];
    const float* Wi  = (const float*)d_in[1];
    const int*   obs = (const int*)d_in[2];
    float*       out = (float*)d_out;

    gemm_kernel<<<dim3(CM_B, 5), 256>>>(X, Wi, obs);
    scan_kernel<<<dim3(CM_B * 4), SC_THREADS>>>(out);
}

// round 12
// speedup vs baseline: 1.1946x; 1.1946x over previous
#include <cuda_runtime.h>
#include <cuda_bf16.h>
#include <cstdint>

#define CM_B    64
#define CM_T    256
#define CM_NI   512
#define CM_NO   512
#define CM_NOBS 128
#define ETA     0.01f

typedef unsigned long long u64;

// Scratch: C[b][m][n], m<256 -> G[s=m][t=n]; m>=256 -> P0[o=m-256][t=n]
__device__ float g_scratch[(size_t)CM_B * 384 * 256];

// ---------------- helpers ----------------
__device__ __forceinline__ u64 pk2(float lo, float hi) {
    u64 r; asm("mov.b64 %0, {%1, %2};" : "=l"(r) : "f"(lo), "f"(hi)); return r;
}
__device__ __forceinline__ float2 upk2(u64 v) {
    float2 f; asm("mov.b64 {%0, %1}, %2;" : "=f"(f.x), "=f"(f.y) : "l"(v)); return f;
}
__device__ __forceinline__ u64 ffma2(u64 a, u64 b, u64 c) {
    u64 d; asm("fma.rn.f32x2 %0, %1, %2, %3;" : "=l"(d) : "l"(a), "l"(b), "l"(c)); return d;
}
__device__ __forceinline__ float sigmoidf_fast(float v) {
    return __fdividef(1.0f, 1.0f + __expf(-v));
}
// mma m16n8k16 bf16, D += A*B
__device__ __forceinline__ void mma16(float& d0, float& d1, float& d2, float& d3,
                                      uint32_t a0, uint32_t a1, uint32_t a2, uint32_t a3,
                                      uint32_t b0, uint32_t b1) {
    asm volatile(
        "mma.sync.aligned.m16n8k16.row.col.f32.bf16.bf16.f32 "
        "{%0,%1,%2,%3}, {%4,%5,%6,%7}, {%8,%9}, {%0,%1,%2,%3};"
        : "+f"(d0), "+f"(d1), "+f"(d2), "+f"(d3)
        : "r"(a0), "r"(a1), "r"(a2), "r"(a3), "r"(b0), "r"(b1));
}

// ---------------- Kernel 1: batched GEMM C = [X;W_obs] * X^T (bf16x3) ----------------
#define KC   32
#define SBF  40        // bf16 row stride (80B): conflict-free fragment pattern

__constant__ int c_mt[5] = {0, 0, 1, 2, 2};
__constant__ int c_nt[5] = {0, 1, 1, 0, 1};

__global__ __launch_bounds__(256)
void gemm_kernel(const float* __restrict__ X,
                 const float* __restrict__ Wi,
                 const int*   __restrict__ obs) {
    __shared__ __align__(16) __nv_bfloat16 Ah[128 * SBF], Al[128 * SBF];
    __shared__ __align__(16) __nv_bfloat16 Bh[128 * SBF], Bl[128 * SBF];

    const int b     = blockIdx.x;
    const int mtile = c_mt[blockIdx.y];
    const int ntile = c_nt[blockIdx.y];

    const int tid  = threadIdx.x;
    const int warp = tid >> 5, lane = tid & 31;
    const int wm   = warp >> 1, wn = warp & 1;      // 4x2 warps over 128x128
    const int gID  = lane >> 2, tig = lane & 3;

    const int lrow  = tid >> 1;
    const int lcol0 = (tid & 1) * 16;
    const int arow  = mtile * 128 + lrow;
    const float* aptr = (arow < 256)
        ? X  + ((size_t)b * CM_T  + arow) * CM_NI
        : Wi + ((size_t)b * CM_NO + __ldg(&obs[arow - 256])) * CM_NI;
    const float* bptr = X + ((size_t)b * CM_T + ntile * 128 + lrow) * CM_NI;

    float acc[2][8][4];
    #pragma unroll
    for (int i = 0; i < 2; ++i)
        #pragma unroll
        for (int j = 0; j < 8; ++j)
            #pragma unroll
            for (int q = 0; q < 4; ++q) acc[i][j][q] = 0.f;

    for (int ks = 0; ks < CM_NI; ks += KC) {
        // stage + split A and B (each thread: 16 cols of one row)
        #pragma unroll
        for (int h = 0; h < 4; ++h) {
            float4 v = *(const float4*)(aptr + ks + lcol0 + h * 4);
            __nv_bfloat162 hp0 = __floats2bfloat162_rn(v.x, v.y);
            __nv_bfloat162 hp1 = __floats2bfloat162_rn(v.z, v.w);
            float2 f0 = __bfloat1622float2(hp0), f1 = __bfloat1622float2(hp1);
            __nv_bfloat162 lp0 = __floats2bfloat162_rn(v.x - f0.x, v.y - f0.y);
            __nv_bfloat162 lp1 = __floats2bfloat162_rn(v.z - f1.x, v.w - f1.y);
            __nv_bfloat16* dh = Ah + lrow * SBF + lcol0 + h * 4;
            __nv_bfloat16* dl = Al + lrow * SBF + lcol0 + h * 4;
            *(__nv_bfloat162*)(dh)     = hp0; *(__nv_bfloat162*)(dh + 2) = hp1;
            *(__nv_bfloat162*)(dl)     = lp0; *(__nv_bfloat162*)(dl + 2) = lp1;
        }
        #pragma unroll
        for (int h = 0; h < 4; ++h) {
            float4 v = *(const float4*)(bptr + ks + lcol0 + h * 4);
            __nv_bfloat162 hp0 = __floats2bfloat162_rn(v.x, v.y);
            __nv_bfloat162 hp1 = __floats2bfloat162_rn(v.z, v.w);
            float2 f0 = __bfloat1622float2(hp0), f1 = __bfloat1622float2(hp1);
            __nv_bfloat162 lp0 = __floats2bfloat162_rn(v.x - f0.x, v.y - f0.y);
            __nv_bfloat162 lp1 = __floats2bfloat162_rn(v.z - f1.x, v.w - f1.y);
            __nv_bfloat16* dh = Bh + lrow * SBF + lcol0 + h * 4;
            __nv_bfloat16* dl = Bl + lrow * SBF + lcol0 + h * 4;
            *(__nv_bfloat162*)(dh)     = hp0; *(__nv_bfloat162*)(dh + 2) = hp1;
            *(__nv_bfloat162*)(dl)     = lp0; *(__nv_bfloat162*)(dl + 2) = lp1;
        }
        __syncthreads();

        #pragma unroll
        for (int kk = 0; kk < KC / 16; ++kk) {
            const int kb = kk * 16;
            uint32_t ahf[2][4], alf[2][4];
            #pragma unroll
            for (int mf = 0; mf < 2; ++mf) {
                const int m0 = wm * 32 + mf * 16;
                const int r0 = (m0 + gID) * SBF + kb + 2 * tig;
                const int r1 = (m0 + gID + 8) * SBF + kb + 2 * tig;
                ahf[mf][0] = *(const uint32_t*)(Ah + r0);
                ahf[mf][1] = *(const uint32_t*)(Ah + r1);
                ahf[mf][2] = *(const uint32_t*)(Ah + r0 + 8);
                ahf[mf][3] = *(const uint32_t*)(Ah + r1 + 8);
                alf[mf][0] = *(const uint32_t*)(Al + r0);
                alf[mf][1] = *(const uint32_t*)(Al + r1);
                alf[mf][2] = *(const uint32_t*)(Al + r0 + 8);
                alf[mf][3] = *(const uint32_t*)(Al + r1 + 8);
            }
            #pragma unroll
            for (int nf = 0; nf < 8; ++nf) {
                const int n0 = wn * 64 + nf * 8;
                const int rb = (n0 + gID) * SBF + kb + 2 * tig;
                uint32_t bh0 = *(const uint32_t*)(Bh + rb);
                uint32_t bh1 = *(const uint32_t*)(Bh + rb + 8);
                uint32_t bl0 = *(const uint32_t*)(Bl + rb);
                uint32_t bl1 = *(const uint32_t*)(Bl + rb + 8);
                #pragma unroll
                for (int mf = 0; mf < 2; ++mf) {
                    float* d = acc[mf][nf];
                    mma16(d[0], d[1], d[2], d[3],
                          ahf[mf][0], ahf[mf][1], ahf[mf][2], ahf[mf][3], bh0, bh1);
                    mma16(d[0], d[1], d[2], d[3],
                          ahf[mf][0], ahf[mf][1], ahf[mf][2], ahf[mf][3], bl0, bl1);
                    mma16(d[0], d[1], d[2], d[3],
                          alf[mf][0], alf[mf][1], alf[mf][2], alf[mf][3], bh0, bh1);
                }
            }
        }
        __syncthreads();
    }

    #pragma unroll
    for (int mf = 0; mf < 2; ++mf) {
        const int mrow = mtile * 128 + wm * 32 + mf * 16 + gID;
        #pragma unroll
        for (int nf = 0; nf < 8; ++nf) {
            const int ncol = ntile * 128 + wn * 64 + nf * 8 + 2 * tig;
            float* cp = g_scratch + ((size_t)b * 384 + mrow) * 256 + ncol;
            *(float2*)cp             = make_float2(acc[mf][nf][0], acc[mf][nf][1]);
            *(float2*)(cp + 8 * 256) = make_float2(acc[mf][nf][2], acc[mf][nf][3]);
        }
    }
}

// ---------------- Kernel 2: blocked causal scan (pre in registers) ----------------
// Block = (batch, quarter): 32 rows, 128 threads. Thread tid owns t = {2tid, 2tid+1}
// for ALL 32 rows: pre[o] packed f32x2. G read from global (coalesced, L2-hot).
__global__ __launch_bounds__(128)
void scan_kernel(float* __restrict__ out) {
    __shared__ u64   ych[8][32];     // prepacked (eta*y, eta*y) per (s, o)
    __shared__ float ser[8][33];     // serial-phase pre handoff

    const int bb    = blockIdx.x;
    const int b     = bb >> 2;
    const int obase = (bb & 3) * 32;
    const int tid   = threadIdx.x;

    const float* P0 = g_scratch + ((size_t)b * 384 + 256 + obase) * 256;
    const float* G  = g_scratch + (size_t)b * 384 * 256;
    float* outp     = out + (size_t)b * CM_T * CM_NOBS + obase;

    u64 pre[32];
    #pragma unroll
    for (int o = 0; o < 32; ++o)
        pre[o] = *(const u64*)(P0 + o * 256 + 2 * tid);

    #pragma unroll 1
    for (int k = 0; k < 32; ++k) {
        const int t0     = k * 8;
        const int towner = t0 >> 1;

        // hand off this chunk's pre values (4 owning threads)
        if (tid >= towner && tid < towner + 4) {
            const int s0 = (tid - towner) * 2;
            #pragma unroll
            for (int o = 0; o < 32; ++o) {
                float2 v = upk2(pre[o]);
                ser[s0][o] = v.x; ser[s0 + 1][o] = v.y;
            }
        }
        __syncthreads();

        // serial phase: thread o (<32) runs the 8-step recurrence for its row
        if (tid < 32) {
            const int o = tid;
            float p[8];
            #pragma unroll
            for (int s = 0; s < 8; ++s) p[s] = ser[s][o];
            #pragma unroll
            for (int s = 0; s < 8; ++s) {
                const float y = sigmoidf_fast(p[s]);
                outp[(size_t)(t0 + s) * CM_NOBS + o] = y;
                const float c = ETA * y;
                ych[s][o] = pk2(c, c);
                #pragma unroll
                for (int s2 = s + 1; s2 < 8; ++s2)
                    p[s2] += c * __ldg(&G[(size_t)(t0 + s) * 256 + t0 + s2]);
            }
        }
        __syncthreads();

        // bulk: threads with t >= t0+8 update their pre slices
        if (tid >= towner + 4) {
            u64 g2[8];
            #pragma unroll
            for (int s = 0; s < 8; ++s)
                g2[s] = *(const u64*)(G + (size_t)(t0 + s) * 256 + 2 * tid);
            #pragma unroll
            for (int s = 0; s < 8; ++s) {
                const ulonglong2* cp = (const ulonglong2*)(&ych[s][0]);
                #pragma unroll
                for (int op = 0; op < 16; ++op) {
                    ulonglong2 c = cp[op];                 // coefs for o=2op, 2op+1
                    pre[2 * op]     = ffma2(c.x, g2[s], pre[2 * op]);
                    pre[2 * op + 1] = ffma2(c.y, g2[s], pre[2 * op + 1]);
                }
            }
        }
        __syncthreads();
    }
}

// ---------------- launch ----------------
extern "C" void kernel_launch(void* const* d_in, const int* in_sizes, int n_in,
                              void* d_out, int out_size) {
    const float* X   = (const float*)d_in[0];
    const float* Wi  = (const float*)d_in[1];
    const int*   obs = (const int*)d_in[2];
    float*       out = (float*)d_out;

    gemm_kernel<<<dim3(CM_B, 5), 256>>>(X, Wi, obs);
    scan_kernel<<<dim3(CM_B * 4), 128>>>(out);
}

// round 13
// speedup vs baseline: 1.5441x; 1.2925x over previous
#include <cuda_runtime.h>
#include <cuda_bf16.h>
#include <cstdint>

#define CM_B    64
#define CM_T    256
#define CM_NI   512
#define CM_NO   512
#define CM_NOBS 128
#define ETA     0.01f

typedef unsigned long long u64;

// Scratch: C[b][m][n], m<256 -> G[s=m][t=n]; m>=256 -> P0[o=m-256][t=n]
__device__ float g_scratch[(size_t)CM_B * 384 * 256];

// ---------------- helpers ----------------
__device__ __forceinline__ u64 pk2(float lo, float hi) {
    u64 r; asm("mov.b64 %0, {%1, %2};" : "=l"(r) : "f"(lo), "f"(hi)); return r;
}
__device__ __forceinline__ float2 upk2(u64 v) {
    float2 f; asm("mov.b64 {%0, %1}, %2;" : "=f"(f.x), "=f"(f.y) : "l"(v)); return f;
}
__device__ __forceinline__ u64 ffma2(u64 a, u64 b, u64 c) {
    u64 d; asm("fma.rn.f32x2 %0, %1, %2, %3;" : "=l"(d) : "l"(a), "l"(b), "l"(c)); return d;
}
__device__ __forceinline__ float sigmoidf_fast(float v) {
    return __fdividef(1.0f, 1.0f + __expf(-v));
}
// mma m16n8k16 bf16, D += A*B
__device__ __forceinline__ void mma16(float& d0, float& d1, float& d2, float& d3,
                                      uint32_t a0, uint32_t a1, uint32_t a2, uint32_t a3,
                                      uint32_t b0, uint32_t b1) {
    asm volatile(
        "mma.sync.aligned.m16n8k16.row.col.f32.bf16.bf16.f32 "
        "{%0,%1,%2,%3}, {%4,%5,%6,%7}, {%8,%9}, {%0,%1,%2,%3};"
        : "+f"(d0), "+f"(d1), "+f"(d2), "+f"(d3)
        : "r"(a0), "r"(a1), "r"(a2), "r"(a3), "r"(b0), "r"(b1));
}

// ---------------- Kernel 1: batched GEMM C = [X;W_obs] * X^T (bf16x3) ----------------
#define KC   32
#define SBF  40        // bf16 row stride (80B): conflict-free fragment pattern

__constant__ int c_mt[5] = {0, 0, 1, 2, 2};
__constant__ int c_nt[5] = {0, 1, 1, 0, 1};

__global__ __launch_bounds__(256)
void gemm_kernel(const float* __restrict__ X,
                 const float* __restrict__ Wi,
                 const int*   __restrict__ obs) {
    __shared__ __align__(16) __nv_bfloat16 Ah[128 * SBF], Al[128 * SBF];
    __shared__ __align__(16) __nv_bfloat16 Bh[128 * SBF], Bl[128 * SBF];

    const int b     = blockIdx.x;
    const int mtile = c_mt[blockIdx.y];
    const int ntile = c_nt[blockIdx.y];

    const int tid  = threadIdx.x;
    const int warp = tid >> 5, lane = tid & 31;
    const int wm   = warp >> 1, wn = warp & 1;      // 4x2 warps over 128x128
    const int gID  = lane >> 2, tig = lane & 3;

    const int lrow  = tid >> 1;
    const int lcol0 = (tid & 1) * 16;
    const int arow  = mtile * 128 + lrow;
    const float* aptr = (arow < 256)
        ? X  + ((size_t)b * CM_T  + arow) * CM_NI
        : Wi + ((size_t)b * CM_NO + __ldg(&obs[arow - 256])) * CM_NI;
    const float* bptr = X + ((size_t)b * CM_T + ntile * 128 + lrow) * CM_NI;

    float acc[2][8][4];
    #pragma unroll
    for (int i = 0; i < 2; ++i)
        #pragma unroll
        for (int j = 0; j < 8; ++j)
            #pragma unroll
            for (int q = 0; q < 4; ++q) acc[i][j][q] = 0.f;

    for (int ks = 0; ks < CM_NI; ks += KC) {
        #pragma unroll
        for (int h = 0; h < 4; ++h) {
            float4 v = *(const float4*)(aptr + ks + lcol0 + h * 4);
            __nv_bfloat162 hp0 = __floats2bfloat162_rn(v.x, v.y);
            __nv_bfloat162 hp1 = __floats2bfloat162_rn(v.z, v.w);
            float2 f0 = __bfloat1622float2(hp0), f1 = __bfloat1622float2(hp1);
            __nv_bfloat162 lp0 = __floats2bfloat162_rn(v.x - f0.x, v.y - f0.y);
            __nv_bfloat162 lp1 = __floats2bfloat162_rn(v.z - f1.x, v.w - f1.y);
            __nv_bfloat16* dh = Ah + lrow * SBF + lcol0 + h * 4;
            __nv_bfloat16* dl = Al + lrow * SBF + lcol0 + h * 4;
            *(__nv_bfloat162*)(dh)     = hp0; *(__nv_bfloat162*)(dh + 2) = hp1;
            *(__nv_bfloat162*)(dl)     = lp0; *(__nv_bfloat162*)(dl + 2) = lp1;
        }
        #pragma unroll
        for (int h = 0; h < 4; ++h) {
            float4 v = *(const float4*)(bptr + ks + lcol0 + h * 4);
            __nv_bfloat162 hp0 = __floats2bfloat162_rn(v.x, v.y);
            __nv_bfloat162 hp1 = __floats2bfloat162_rn(v.z, v.w);
            float2 f0 = __bfloat1622float2(hp0), f1 = __bfloat1622float2(hp1);
            __nv_bfloat162 lp0 = __floats2bfloat162_rn(v.x - f0.x, v.y - f0.y);
            __nv_bfloat162 lp1 = __floats2bfloat162_rn(v.z - f1.x, v.w - f1.y);
            __nv_bfloat16* dh = Bh + lrow * SBF + lcol0 + h * 4;
            __nv_bfloat16* dl = Bl + lrow * SBF + lcol0 + h * 4;
            *(__nv_bfloat162*)(dh)     = hp0; *(__nv_bfloat162*)(dh + 2) = hp1;
            *(__nv_bfloat162*)(dl)     = lp0; *(__nv_bfloat162*)(dl + 2) = lp1;
        }
        __syncthreads();

        #pragma unroll
        for (int kk = 0; kk < KC / 16; ++kk) {
            const int kb = kk * 16;
            uint32_t ahf[2][4], alf[2][4];
            #pragma unroll
            for (int mf = 0; mf < 2; ++mf) {
                const int m0 = wm * 32 + mf * 16;
                const int r0 = (m0 + gID) * SBF + kb + 2 * tig;
                const int r1 = (m0 + gID + 8) * SBF + kb + 2 * tig;
                ahf[mf][0] = *(const uint32_t*)(Ah + r0);
                ahf[mf][1] = *(const uint32_t*)(Ah + r1);
                ahf[mf][2] = *(const uint32_t*)(Ah + r0 + 8);
                ahf[mf][3] = *(const uint32_t*)(Ah + r1 + 8);
                alf[mf][0] = *(const uint32_t*)(Al + r0);
                alf[mf][1] = *(const uint32_t*)(Al + r1);
                alf[mf][2] = *(const uint32_t*)(Al + r0 + 8);
                alf[mf][3] = *(const uint32_t*)(Al + r1 + 8);
            }
            #pragma unroll
            for (int nf = 0; nf < 8; ++nf) {
                const int n0 = wn * 64 + nf * 8;
                const int rb = (n0 + gID) * SBF + kb + 2 * tig;
                uint32_t bh0 = *(const uint32_t*)(Bh + rb);
                uint32_t bh1 = *(const uint32_t*)(Bh + rb + 8);
                uint32_t bl0 = *(const uint32_t*)(Bl + rb);
                uint32_t bl1 = *(const uint32_t*)(Bl + rb + 8);
                #pragma unroll
                for (int mf = 0; mf < 2; ++mf) {
                    float* d = acc[mf][nf];
                    mma16(d[0], d[1], d[2], d[3],
                          ahf[mf][0], ahf[mf][1], ahf[mf][2], ahf[mf][3], bh0, bh1);
                    mma16(d[0], d[1], d[2], d[3],
                          ahf[mf][0], ahf[mf][1], ahf[mf][2], ahf[mf][3], bl0, bl1);
                    mma16(d[0], d[1], d[2], d[3],
                          alf[mf][0], alf[mf][1], alf[mf][2], alf[mf][3], bh0, bh1);
                }
            }
        }
        __syncthreads();
    }

    #pragma unroll
    for (int mf = 0; mf < 2; ++mf) {
        const int mrow = mtile * 128 + wm * 32 + mf * 16 + gID;
        #pragma unroll
        for (int nf = 0; nf < 8; ++nf) {
            const int ncol = ntile * 128 + wn * 64 + nf * 8 + 2 * tig;
            float* cp = g_scratch + ((size_t)b * 384 + mrow) * 256 + ncol;
            *(float2*)cp             = make_float2(acc[mf][nf][0], acc[mf][nf][1]);
            *(float2*)(cp + 8 * 256) = make_float2(acc[mf][nf][2], acc[mf][nf][3]);
        }
    }
}

// ---------------- Kernel 2: blocked causal scan (deep prefetch, 16 rows/block) ----------------
// Block = (batch, 1/8 of rows) = 16 rows, 128 threads. Thread owns t-pair {2tid,2tid+1}
// for all 16 rows (pre[16] packed f32x2 in regs). G diagonal triangle -> smem,
// bulk G rows -> regs, both prefetched ONE CHUNK AHEAD (LDGs issued right after
// sync A, covered by the serial phase). No LDG on any dependence chain.
#define SC_ROWS 16

__global__ __launch_bounds__(128)
void scan_kernel(float* __restrict__ out) {
    __shared__ float             tri[8][9];
    __shared__ __align__(16) u64 ych[8][SC_ROWS];
    __shared__ float             ser[8][SC_ROWS + 1];

    const int bb    = blockIdx.x;
    const int b     = bb >> 3;
    const int obase = (bb & 7) * SC_ROWS;
    const int tid   = threadIdx.x;

    const float* P0 = g_scratch + ((size_t)b * 384 + 256 + obase) * 256;
    const float* G  = g_scratch + (size_t)b * 384 * 256;
    float* outp     = out + (size_t)b * CM_T * CM_NOBS + obase;

    u64 pre[SC_ROWS];
    #pragma unroll
    for (int o = 0; o < SC_ROWS; ++o)
        pre[o] = *(const u64*)(P0 + o * 256 + 2 * tid);

    // prologue prefetch: chunk-0 triangle + chunk-0 bulk rows
    float trn = 0.f;
    if (tid < 64) trn = __ldg(&G[(size_t)(tid >> 3) * 256 + (tid & 7)]);
    u64 g2c[8];
    #pragma unroll
    for (int s = 0; s < 8; ++s)
        g2c[s] = *(const u64*)(G + (size_t)s * 256 + 2 * tid);

    #pragma unroll 1
    for (int k = 0; k < 32; ++k) {
        const int t0     = k * 8;
        const int towner = t0 >> 1;

        // handoff: owners publish this chunk's pre values
        if (tid >= towner && tid < towner + 4) {
            const int s0 = (tid - towner) * 2;
            #pragma unroll
            for (int o = 0; o < SC_ROWS; ++o) {
                float2 v = upk2(pre[o]);
                ser[s0][o] = v.x; ser[s0 + 1][o] = v.y;
            }
        }
        if (tid < 64) tri[tid >> 3][tid & 7] = trn;   // prefetched last iter
        __syncthreads();   // A

        // issue next-chunk prefetches NOW (fly during serial phase)
        const int t0n = (k < 31) ? t0 + 8 : t0;
        u64 g2n[8];
        #pragma unroll
        for (int s = 0; s < 8; ++s)
            g2n[s] = *(const u64*)(G + (size_t)(t0n + s) * 256 + 2 * tid);
        if (tid < 64) trn = __ldg(&G[(size_t)(t0n + (tid >> 3)) * 256 + t0n + (tid & 7)]);

        // serial: thread o runs the 8-step recurrence (smem triangle only)
        if (tid < SC_ROWS) {
            const int o = tid;
            float p[8];
            #pragma unroll
            for (int s = 0; s < 8; ++s) p[s] = ser[s][o];
            #pragma unroll
            for (int s = 0; s < 8; ++s) {
                const float y = sigmoidf_fast(p[s]);
                outp[(size_t)(t0 + s) * CM_NOBS + o] = y;
                const float c = ETA * y;
                ych[s][o] = pk2(c, c);
                #pragma unroll
                for (int s2 = s + 1; s2 < 8; ++s2)
                    p[s2] += c * tri[s][s2];
            }
        }
        __syncthreads();   // B

        // bulk: update pre for t >= t0+8 with prefetched G rows
        if (tid >= towner + 4) {
            #pragma unroll
            for (int s = 0; s < 8; ++s) {
                const ulonglong2* cp = (const ulonglong2*)(&ych[s][0]);
                const u64 g = g2c[s];
                #pragma unroll
                for (int op = 0; op < SC_ROWS / 2; ++op) {
                    ulonglong2 c = cp[op];
                    pre[2 * op]     = ffma2(c.x, g, pre[2 * op]);
                    pre[2 * op + 1] = ffma2(c.y, g, pre[2 * op + 1]);
                }
            }
        }
        #pragma unroll
        for (int s = 0; s < 8; ++s) g2c[s] = g2n[s];
    }
}

// ---------------- launch ----------------
extern "C" void kernel_launch(void* const* d_in, const int* in_sizes, int n_in,
                              void* d_out, int out_size) {
    const float* X   = (const float*)d_in[0];
    const float* Wi  = (const float*)d_in[1];
    const int*   obs = (const int*)d_in[2];
    float*       out = (float*)d_out;

    gemm_kernel<<<dim3(CM_B, 5), 256>>>(X, Wi, obs);
    scan_kernel<<<dim3(CM_B * 8), 128>>>(out);
}